// round 2
// baseline (speedup 1.0000x reference)
#include <cuda_runtime.h>
#include <math.h>

#define B_  4
#define S_  2048
#define D_  1024
#define H_  16
#define HD_ 64

// Scratch (allocation-free rule: __device__ globals)
__device__ float g_K[B_*H_*HD_*S_];   // [b][h][d][s]  (transposed for attn)
__device__ float g_V[B_*H_*S_*HD_];   // [b][h][s][d]
__device__ float g_Q[B_*H_*HD_*S_];   // [b][h][d][s]  (transposed for attn)
__device__ float g_ctx[B_*S_*D_];     // [b][s][h*HD+d]

// ---------------------------------------------------------------------------
// GEMM: C = A(MxK) @ W(KxN) + bias, fp32 SIMT, BM=128 BN=64 BK=16, 8x4 micro.
// MODE 0: KV projection -> split into g_K (transposed) / g_V (natural)
// MODE 1: Q projection  -> g_Q (transposed)
// MODE 2: plain row-major store to out0
// ---------------------------------------------------------------------------
template<int MODE>
__global__ void __launch_bounds__(256) gemm_kernel(
    const float* __restrict__ A, const float* __restrict__ W,
    const float* __restrict__ bias, float* __restrict__ out0,
    float* __restrict__ out1, int M, int N, int K)
{
    __shared__ float As[16][128];   // [k][m]
    __shared__ float Bs[16][64];    // [k][n]

    const int tid = threadIdx.x;
    const int tr  = tid >> 4;       // 0..15  (8 rows each)
    const int tc  = tid & 15;       // 0..15  (4 cols each)
    const int m0  = blockIdx.y * 128;
    const int n0  = blockIdx.x * 64;

    const int ar0 = tid >> 2;            // 0..63
    const int ak  = (tid & 3) * 4;       // 0,4,8,12
    const float* Ap = A + (size_t)(m0 + ar0) * K + ak;
    const float* Bp = W + (size_t)(tid >> 4) * N + n0 + (tid & 15) * 4;

    float acc[8][4];
    #pragma unroll
    for (int r = 0; r < 8; r++)
        #pragma unroll
        for (int c = 0; c < 4; c++) acc[r][c] = 0.f;

    const int nk = K >> 4;
    for (int kt = 0; kt < nk; kt++) {
        float4 a0 = *(const float4*)(Ap);
        float4 a1 = *(const float4*)(Ap + (size_t)64 * K);
        float4 b0 = *(const float4*)(Bp);
        Ap += 16;
        Bp += (size_t)16 * N;

        __syncthreads();
        As[ak+0][ar0] = a0.x; As[ak+1][ar0] = a0.y;
        As[ak+2][ar0] = a0.z; As[ak+3][ar0] = a0.w;
        As[ak+0][ar0+64] = a1.x; As[ak+1][ar0+64] = a1.y;
        As[ak+2][ar0+64] = a1.z; As[ak+3][ar0+64] = a1.w;
        *(float4*)&Bs[tid >> 4][(tid & 15) * 4] = b0;
        __syncthreads();

        #pragma unroll
        for (int kk = 0; kk < 16; kk++) {
            float4 aA = *(const float4*)&As[kk][tr*8];
            float4 aB = *(const float4*)&As[kk][tr*8 + 4];
            float4 bb = *(const float4*)&Bs[kk][tc*4];
            float af[8] = {aA.x, aA.y, aA.z, aA.w, aB.x, aB.y, aB.z, aB.w};
            float bf[4] = {bb.x, bb.y, bb.z, bb.w};
            #pragma unroll
            for (int r = 0; r < 8; r++)
                #pragma unroll
                for (int c = 0; c < 4; c++)
                    acc[r][c] = fmaf(af[r], bf[c], acc[r][c]);
        }
    }

    // ---- epilogue ----
    const int bi     = m0 >> 11;          // batch (S_=2048)
    const int s_base = (m0 & (S_-1)) + tr * 8;
    const int n_base = n0 + tc * 4;
    float4 bv = *(const float4*)&bias[n_base];
    float bb4[4] = {bv.x, bv.y, bv.z, bv.w};

    if (MODE == 0) {
        if ((n0 & 64) == 0) {
            // K half -> transposed store [b][h][d][s]
            #pragma unroll
            for (int c = 0; c < 4; c++) {
                int n = n_base + c;
                int h = n >> 7, d = n & 63;
                float* dst = out0 + ((size_t)(bi*H_ + h) * HD_ + d) * S_ + s_base;
                float4 v0 = {acc[0][c]+bb4[c], acc[1][c]+bb4[c], acc[2][c]+bb4[c], acc[3][c]+bb4[c]};
                float4 v1 = {acc[4][c]+bb4[c], acc[5][c]+bb4[c], acc[6][c]+bb4[c], acc[7][c]+bb4[c]};
                *(float4*)(dst)     = v0;
                *(float4*)(dst + 4) = v1;
            }
        } else {
            // V half -> natural store [b][h][s][d]
            int h  = n_base >> 7;
            int c0 = n_base & 63;
            #pragma unroll
            for (int r = 0; r < 8; r++) {
                float4 v = {acc[r][0]+bb4[0], acc[r][1]+bb4[1], acc[r][2]+bb4[2], acc[r][3]+bb4[3]};
                *(float4*)(out1 + ((size_t)(bi*H_ + h) * S_ + s_base + r) * HD_ + c0) = v;
            }
        }
    } else if (MODE == 1) {
        // Q -> transposed store [b][h][d][s]
        #pragma unroll
        for (int c = 0; c < 4; c++) {
            int n = n_base + c;
            int h = n >> 6, d = n & 63;
            float* dst = out0 + ((size_t)(bi*H_ + h) * HD_ + d) * S_ + s_base;
            float4 v0 = {acc[0][c]+bb4[c], acc[1][c]+bb4[c], acc[2][c]+bb4[c], acc[3][c]+bb4[c]};
            float4 v1 = {acc[4][c]+bb4[c], acc[5][c]+bb4[c], acc[6][c]+bb4[c], acc[7][c]+bb4[c]};
            *(float4*)(dst)     = v0;
            *(float4*)(dst + 4) = v1;
        }
    } else {
        #pragma unroll
        for (int r = 0; r < 8; r++) {
            float4 v = {acc[r][0]+bb4[0], acc[r][1]+bb4[1], acc[r][2]+bb4[2], acc[r][3]+bb4[3]};
            *(float4*)(out0 + (size_t)(m0 + tr*8 + r) * N + n_base) = v;
        }
    }
}

// ---------------------------------------------------------------------------
// Flash attention: one block = (b, h, 64-query tile). BM=BN=64, online softmax.
// Q,K in [b][h][d][s]; V in [b][h][s][d]; mask tile buffer reused as P tile.
// ---------------------------------------------------------------------------
__global__ void __launch_bounds__(256) attn_kernel(
    const float* __restrict__ gK, const float* __restrict__ gV,
    const float* __restrict__ gQ, const float* __restrict__ mask,
    float* __restrict__ ctx)
{
    extern __shared__ float sm[];
    float* Qs = sm;            // [64][64]  [d][i]
    float* Ks = sm + 4096;     // [64][64]  [d][j]
    float* Vs = sm + 8192;     // [64][64]  [j][d]
    float* PM = sm + 12288;    // [64][64]  [i][j]  mask, then P

    const int tid = threadIdx.x;
    const int tr = tid >> 4, tc = tid & 15;
    const int q0 = blockIdx.x * 64;
    const int h  = blockIdx.y;
    const int b  = blockIdx.z;

    const float* Qb = gQ + (size_t)(b*H_ + h) * HD_ * S_;   // [d][s]
    const float* Kb = gK + (size_t)(b*H_ + h) * HD_ * S_;   // [d][s]
    const float* Vb = gV + (size_t)(b*H_ + h) * S_ * HD_;   // [s][d]

    const int row = tid >> 4;            // 0..15
    const int c4  = (tid & 15) * 4;

    #pragma unroll
    for (int it = 0; it < 4; it++) {
        int d = row + it * 16;
        *(float4*)&Qs[d*64 + c4] = *(const float4*)&Qb[(size_t)d * S_ + q0 + c4];
    }

    float mrow[4], lrow[4], o[4][4];
    #pragma unroll
    for (int r = 0; r < 4; r++) {
        mrow[r] = -INFINITY; lrow[r] = 0.f;
        #pragma unroll
        for (int c = 0; c < 4; c++) o[r][c] = 0.f;
    }

    for (int kt = 0; kt < S_/64; kt++) {
        const int k0 = kt * 64;
        #pragma unroll
        for (int it = 0; it < 4; it++) {
            int rr = row + it * 16;
            *(float4*)&Ks[rr*64 + c4] = *(const float4*)&Kb[(size_t)rr * S_ + k0 + c4];
            *(float4*)&Vs[rr*64 + c4] = *(const float4*)&Vb[(size_t)(k0 + rr) * HD_ + c4];
            *(float4*)&PM[rr*64 + c4] = *(const float4*)&mask[(size_t)(q0 + rr) * S_ + k0 + c4];
        }
        __syncthreads();

        // S = Q^T K (accumulate over d)
        float s[4][4];
        #pragma unroll
        for (int r = 0; r < 4; r++)
            #pragma unroll
            for (int c = 0; c < 4; c++) s[r][c] = 0.f;

        #pragma unroll 8
        for (int d = 0; d < 64; d++) {
            float4 q4 = *(const float4*)&Qs[d*64 + tr*4];
            float4 k4 = *(const float4*)&Ks[d*64 + tc*4];
            float qf[4] = {q4.x, q4.y, q4.z, q4.w};
            float kf[4] = {k4.x, k4.y, k4.z, k4.w};
            #pragma unroll
            for (int r = 0; r < 4; r++)
                #pragma unroll
                for (int c = 0; c < 4; c++)
                    s[r][c] = fmaf(qf[r], kf[c], s[r][c]);
        }

        // scale + mask + online softmax (row groups = 16-lane halves)
        #pragma unroll
        for (int r = 0; r < 4; r++) {
            float4 mk = *(const float4*)&PM[(tr*4 + r)*64 + tc*4];
            s[r][0] = s[r][0]*0.125f + mk.x;
            s[r][1] = s[r][1]*0.125f + mk.y;
            s[r][2] = s[r][2]*0.125f + mk.z;
            s[r][3] = s[r][3]*0.125f + mk.w;

            float tmax = fmaxf(fmaxf(s[r][0], s[r][1]), fmaxf(s[r][2], s[r][3]));
            #pragma unroll
            for (int off = 8; off >= 1; off >>= 1)
                tmax = fmaxf(tmax, __shfl_xor_sync(0xffffffffu, tmax, off, 16));

            float newm = fmaxf(mrow[r], tmax);
            float corr = __expf(mrow[r] - newm);
            mrow[r] = newm;

            float p0 = __expf(s[r][0] - newm);
            float p1 = __expf(s[r][1] - newm);
            float p2 = __expf(s[r][2] - newm);
            float p3 = __expf(s[r][3] - newm);
            float psum = p0 + p1 + p2 + p3;
            #pragma unroll
            for (int off = 8; off >= 1; off >>= 1)
                psum += __shfl_xor_sync(0xffffffffu, psum, off, 16);

            lrow[r] = lrow[r]*corr + psum;
            #pragma unroll
            for (int c = 0; c < 4; c++) o[r][c] *= corr;

            float4 pv = {p0, p1, p2, p3};
            *(float4*)&PM[(tr*4 + r)*64 + tc*4] = pv;   // same elems this thread read
        }
        __syncthreads();

        // O += P @ V
        #pragma unroll 4
        for (int j0 = 0; j0 < 64; j0 += 4) {
            float4 pr[4], vv[4];
            #pragma unroll
            for (int r = 0; r < 4; r++) pr[r] = *(const float4*)&PM[(tr*4 + r)*64 + j0];
            #pragma unroll
            for (int u = 0; u < 4; u++) vv[u] = *(const float4*)&Vs[(j0 + u)*64 + tc*4];
            #pragma unroll
            for (int r = 0; r < 4; r++) {
                float pf[4] = {pr[r].x, pr[r].y, pr[r].z, pr[r].w};
                #pragma unroll
                for (int u = 0; u < 4; u++) {
                    float vf[4] = {vv[u].x, vv[u].y, vv[u].z, vv[u].w};
                    #pragma unroll
                    for (int c = 0; c < 4; c++)
                        o[r][c] = fmaf(pf[u], vf[c], o[r][c]);
                }
            }
        }
        __syncthreads();
    }

    #pragma unroll
    for (int r = 0; r < 4; r++) {
        float inv = 1.f / lrow[r];
        float4 ov = {o[r][0]*inv, o[r][1]*inv, o[r][2]*inv, o[r][3]*inv};
        *(float4*)&ctx[((size_t)(b*S_) + q0 + tr*4 + r) * D_ + h*HD_ + tc*4] = ov;
    }
}

// ---------------------------------------------------------------------------
extern "C" void kernel_launch(void* const* d_in, const int* in_sizes, int n_in,
                              void* d_out, int out_size)
{
    const float* x    = (const float*)d_in[0];
    const float* y    = (const float*)d_in[1];
    const float* mask = (const float*)d_in[2];
    const float* Wkv  = (const float*)d_in[3];
    const float* bkv  = (const float*)d_in[4];
    const float* Wq   = (const float*)d_in[5];
    const float* bq   = (const float*)d_in[6];
    const float* Wo   = (const float*)d_in[7];
    const float* bo   = (const float*)d_in[8];
    float* out = (float*)d_out;

    float *pK, *pV, *pQ, *pC;
    cudaGetSymbolAddress((void**)&pK, g_K);
    cudaGetSymbolAddress((void**)&pV, g_V);
    cudaGetSymbolAddress((void**)&pQ, g_Q);
    cudaGetSymbolAddress((void**)&pC, g_ctx);

    cudaFuncSetAttribute(attn_kernel, cudaFuncAttributeMaxDynamicSharedMemorySize, 65536);

    // KV projection: M=8192, N=2048, K=1024
    gemm_kernel<0><<<dim3(2048/64, 8192/128), 256>>>(x, Wkv, bkv, pK, pV, B_*S_, 2*D_, D_);
    // Q projection: M=8192, N=1024, K=1024
    gemm_kernel<1><<<dim3(1024/64, 8192/128), 256>>>(y, Wq, bq, pQ, nullptr, B_*S_, D_, D_);
    // Attention
    attn_kernel<<<dim3(S_/64, H_, B_), 256, 65536>>>(pK, pV, pQ, mask, pC);
    // Output projection: M=8192, N=1024, K=1024
    gemm_kernel<2><<<dim3(1024/64, 8192/128), 256>>>(pC, Wo, bo, out, nullptr, B_*S_, D_, D_);
}